// round 11
// baseline (speedup 1.0000x reference)
#include <cuda_runtime.h>
#include <mma.h>
#include <cstdint>

using namespace nvcuda;

// ---------------- weight layout (floats), strides 68 / 20, all conflict-free --
#define OFF_COL0 0          // [64][68]
#define OFF_VIS0 4352       // [48][68]
#define OFF_SIG0 7616       // [32][68]
#define OFF_C1A  9792       // [64][68] col1 rows 0..63
#define OFF_C1B  14144      // [16][68] row0=0, rows1..15 = col1 rows 64..78
#define OFF_SIG1 15232      // [64][20]
#define OFF_VIS1 16512      // [64][20] col0 real
#define OFF_COL2 17792      // [64][20] cols 0..2 real
#define W_TOTAL  19072

__device__ __align__(16) float g_W[W_TOTAL];

__device__ __forceinline__ float tf32r(float x) {
    unsigned u;
    asm("cvt.rna.tf32.f32 %0, %1;" : "=r"(u) : "f"(x));
    return __uint_as_float(u);
}

__global__ void prep_kernel(const float* __restrict__ ws0, const float* __restrict__ ws1,
                            const float* __restrict__ wc0, const float* __restrict__ wc1,
                            const float* __restrict__ wc2, const float* __restrict__ wv0,
                            const float* __restrict__ wv1) {
    int t = threadIdx.x;
    for (int i = t; i < W_TOTAL; i += 256) g_W[i] = 0.f;
    __syncthreads();
    for (int i = t; i < 64 * 64; i += 256) { int k = i >> 6, n = i & 63; g_W[OFF_COL0 + k * 68 + n] = tf32r(wc0[i]); }
    for (int i = t; i < 48 * 64; i += 256) { int k = i >> 6, n = i & 63; g_W[OFF_VIS0 + k * 68 + n] = tf32r(wv0[i]); }
    for (int i = t; i < 32 * 64; i += 256) { int k = i >> 6, n = i & 63; g_W[OFF_SIG0 + k * 68 + n] = tf32r(ws0[i]); }
    for (int i = t; i < 64 * 64; i += 256) { int k = i >> 6, n = i & 63; g_W[OFF_C1A + k * 68 + n] = tf32r(wc1[i]); }
    for (int i = t; i < 15 * 64; i += 256) { int r = i / 64 + 1, n = i % 64; g_W[OFF_C1B + r * 68 + n] = tf32r(wc1[(63 + r) * 64 + n]); }
    for (int i = t; i < 64 * 16; i += 256) { int k = i >> 4, n = i & 15; g_W[OFF_SIG1 + k * 20 + n] = tf32r(ws1[i]); }
    for (int i = t; i < 64; i += 256)      { g_W[OFF_VIS1 + i * 20] = tf32r(wv1[i]); }
    for (int i = t; i < 64 * 3; i += 256)  { int k = i / 3, c = i - k * 3; g_W[OFF_COL2 + k * 20 + c] = tf32r(wc2[i]); }
}

// ---------------- SH degree-4 ----------------
__device__ __forceinline__ void sh16(float x, float y, float z, float* e) {
    float xx = x * x, yy = y * y, zz = z * z;
    float xy = x * y, yz = y * z, xz = x * z;
    e[0]  = 0.28209479177387814f;
    e[1]  = -0.48860251190291987f * y;
    e[2]  = 0.48860251190291987f * z;
    e[3]  = -0.48860251190291987f * x;
    e[4]  = 1.0925484305920792f * xy;
    e[5]  = -1.0925484305920792f * yz;
    e[6]  = 0.94617469575756f * zz - 0.31539156525252005f;
    e[7]  = -1.0925484305920792f * xz;
    e[8]  = 0.5462742152960396f * (xx - yy);
    e[9]  = 0.5900435899266435f * y * (3.0f * xx - yy);
    e[10] = 2.890611442640554f * xy * z;
    e[11] = 0.4570457994644657f * y * (4.0f * zz - xx - yy);
    e[12] = 0.3731763325901154f * z * (2.0f * zz - 3.0f * xx - 3.0f * yy);
    e[13] = 0.4570457994644657f * x * (4.0f * zz - xx - yy);
    e[14] = 1.445305721320277f * z * (xx - yy);
    e[15] = 0.5900435899266435f * x * (xx - 3.0f * yy);
}

// ---------------- smem layout (floats) ----------------
#define SM_BUFA  19072              // [128][68] inputs; geo cols 0..15; col2 partial cols 32..47
#define SM_SIGH  27776              // [128][68] sig_h; later col1_h
#define SM_VISH  36480              // [128][68] vis_h; later vis1 tile
#define SM_COLH  45184              // [128][68] col0_h; later col2 partial
#define SM_VIS   53888              // [128]
#define SM_TOTAL 54016
#define SMEM_BYTES (SM_TOTAL * 4)

typedef wmma::fragment<wmma::matrix_a, 16, 16, 8, wmma::precision::tf32, wmma::row_major> FragA;
typedef wmma::fragment<wmma::matrix_b, 16, 16, 8, wmma::precision::tf32, wmma::row_major> FragB;
typedef wmma::fragment<wmma::accumulator, 16, 16, 8, float> FragC;

// group barrier: 64 threads (2 warps), barrier id g+1 (8 groups)
#define GBAR() asm volatile("bar.sync %0, %1;" :: "r"(g + 1), "r"(64) : "memory")

__global__ void __launch_bounds__(512, 1)
nerf_wmma(const float* __restrict__ x_feat, const float* __restrict__ dvec,
          const float* __restrict__ lvec, float* __restrict__ out,
          int N, int ntiles) {
    extern __shared__ float sm[];
    float* sW   = sm;
    float* bufA = sm + SM_BUFA;
    float* sigH = sm + SM_SIGH;
    float* visH = sm + SM_VISH;
    float* colH = sm + SM_COLH;
    float* visR = sm + SM_VIS;

    int tid = threadIdx.x, wid = tid >> 5;
    int g = wid >> 1;               // group 0..7, 2 warps each, 16 rows each
    int h = wid & 1;
    int rowM = g * 16;              // the group's 16-row block
    int t2 = tid & 63;              // thread id within group

    {
        const float4* s = (const float4*)g_W;
        float4* d = (float4*)sW;
        for (int i = tid; i < W_TOTAL / 4; i += 512) d[i] = s[i];
    }
    __syncthreads();

    for (int tile = blockIdx.x; tile < ntiles; tile += gridDim.x) {
        // ---- phase 0: group fills its 16 rows of bufA ----
        {
            int r = rowM + (t2 & 15);
            int p = tile * 128 + r;
            int pc = (p < N) ? p : (N - 1);
            if (t2 < 16) {
                const float4* xp = (const float4*)(x_feat + 32 * (size_t)pc);
                float* dst = bufA + r * 68;
#pragma unroll
                for (int i = 0; i < 8; i++) {
                    float4 v = xp[i];
                    dst[4 * i]     = tf32r(v.x);
                    dst[4 * i + 1] = tf32r(v.y);
                    dst[4 * i + 2] = tf32r(v.z);
                    dst[4 * i + 3] = tf32r(v.w);
                }
            } else if (t2 < 32) {
                float e[16];
                const float* lp = lvec + 3 * (size_t)pc;
                sh16(lp[0], lp[1], lp[2], e);
                float* dst = bufA + r * 68 + 32;
#pragma unroll
                for (int i = 0; i < 16; i++) dst[i] = tf32r(e[i]);
            } else if (t2 < 48) {
                float e[16];
                const float* dp = dvec + 3 * (size_t)pc;
                sh16(dp[0], dp[1], dp[2], e);
                float* dst = bufA + r * 68 + 48;
#pragma unroll
                for (int i = 0; i < 16; i++) dst[i] = tf32r(e[i]);
            }
        }
        GBAR();

        // ---- phase 1: A frags hoisted, one accumulator live at a time ----
        {
            FragA a[8];
#pragma unroll
            for (int k = 0; k < 8; k++)
                wmma::load_matrix_sync(a[k], bufA + rowM * 68 + k * 8, 68);
#pragma unroll
            for (int t = 0; t < 2; t++) {
                int nt = 2 * h + t;
                {   // sig0 (K=32)
                    FragC c; wmma::fill_fragment(c, 0.f);
#pragma unroll
                    for (int k = 0; k < 4; k++) {
                        FragB b;
                        wmma::load_matrix_sync(b, sW + OFF_SIG0 + k * 8 * 68 + nt * 16, 68);
                        wmma::mma_sync(c, a[k], b, c);
                    }
#pragma unroll
                    for (int i = 0; i < c.num_elements; i++) c.x[i] = tf32r(fmaxf(c.x[i], 0.f));
                    wmma::store_matrix_sync(sigH + rowM * 68 + nt * 16, c, 68, wmma::mem_row_major);
                }
                {   // vis0 (K=48)
                    FragC c; wmma::fill_fragment(c, 0.f);
#pragma unroll
                    for (int k = 0; k < 6; k++) {
                        FragB b;
                        wmma::load_matrix_sync(b, sW + OFF_VIS0 + k * 8 * 68 + nt * 16, 68);
                        wmma::mma_sync(c, a[k], b, c);
                    }
#pragma unroll
                    for (int i = 0; i < c.num_elements; i++) c.x[i] = tf32r(fmaxf(c.x[i], 0.f));
                    wmma::store_matrix_sync(visH + rowM * 68 + nt * 16, c, 68, wmma::mem_row_major);
                }
                {   // col0 (K=64)
                    FragC c; wmma::fill_fragment(c, 0.f);
#pragma unroll
                    for (int k = 0; k < 8; k++) {
                        FragB b;
                        wmma::load_matrix_sync(b, sW + OFF_COL0 + k * 8 * 68 + nt * 16, 68);
                        wmma::mma_sync(c, a[k], b, c);
                    }
#pragma unroll
                    for (int i = 0; i < c.num_elements; i++) c.x[i] = tf32r(fmaxf(c.x[i], 0.f));
                    wmma::store_matrix_sync(colH + rowM * 68 + nt * 16, c, 68, wmma::mem_row_major);
                }
            }
        }
        GBAR();

        // ---- phase 2: h==0 -> sig1 (geo -> bufA cols 0..15); h==1 -> vis1 ----
        {
            const float* Ain = h ? visH : sigH;
            const float* Bw  = h ? (sW + OFF_VIS1) : (sW + OFF_SIG1);
            FragA a[8];
#pragma unroll
            for (int k = 0; k < 8; k++)
                wmma::load_matrix_sync(a[k], Ain + rowM * 68 + k * 8, 68);
            FragC c;
            wmma::fill_fragment(c, 0.f);
#pragma unroll
            for (int k = 0; k < 8; k++) {
                FragB b;
                wmma::load_matrix_sync(b, Bw + k * 8 * 20, 20);
                wmma::mma_sync(c, a[k], b, c);
            }
            if (h == 0) {   // geo: tf32-round, NO relu
#pragma unroll
                for (int i = 0; i < c.num_elements; i++) c.x[i] = tf32r(c.x[i]);
                wmma::store_matrix_sync(bufA + rowM * 68, c, 68, wmma::mem_row_major);
            } else {        // vis raw logit (col 0 real)
                wmma::store_matrix_sync(visH + rowM * 68, c, 68, wmma::mem_row_major);
            }
        }
        GBAR();
        if (t2 < 16) {
            int r = rowM + t2;
            visR[r] = __fdividef(1.f, 1.f + __expf(-visH[r * 68]));
        }

        // ---- phase 3: col1 = relu(col0_h @ C1A + geo @ C1B) -> sigH ----
        {
            FragA a1[8], a2[2];
#pragma unroll
            for (int k = 0; k < 8; k++)
                wmma::load_matrix_sync(a1[k], colH + rowM * 68 + k * 8, 68);
#pragma unroll
            for (int k = 0; k < 2; k++)
                wmma::load_matrix_sync(a2[k], bufA + rowM * 68 + k * 8, 68);
#pragma unroll
            for (int t = 0; t < 2; t++) {
                int nt = 2 * h + t;
                FragC c; wmma::fill_fragment(c, 0.f);
#pragma unroll
                for (int k = 0; k < 8; k++) {
                    FragB b;
                    wmma::load_matrix_sync(b, sW + OFF_C1A + k * 8 * 68 + nt * 16, 68);
                    wmma::mma_sync(c, a1[k], b, c);
                }
#pragma unroll
                for (int k = 0; k < 2; k++) {
                    FragB b;
                    wmma::load_matrix_sync(b, sW + OFF_C1B + k * 8 * 68 + nt * 16, 68);
                    wmma::mma_sync(c, a2[k], b, c);
                }
#pragma unroll
                for (int i = 0; i < c.num_elements; i++) c.x[i] = tf32r(fmaxf(c.x[i], 0.f));
                wmma::store_matrix_sync(sigH + rowM * 68 + nt * 16, c, 68, wmma::mem_row_major);
            }
        }
        GBAR();

        // ---- phase 4: col2, split-k across h: h==0 k0..3 -> colH; h==1 k4..7 -> bufA+32
        {
            FragA a[4];
#pragma unroll
            for (int k = 0; k < 4; k++)
                wmma::load_matrix_sync(a[k], sigH + rowM * 68 + (h * 4 + k) * 8, 68);
            FragC c;
            wmma::fill_fragment(c, 0.f);
#pragma unroll
            for (int k = 0; k < 4; k++) {
                FragB b;
                wmma::load_matrix_sync(b, sW + OFF_COL2 + (h * 4 + k) * 8 * 20, 20);
                wmma::mma_sync(c, a[k], b, c);
            }
            float* dst = h ? (bufA + rowM * 68 + 32) : (colH + rowM * 68);
            wmma::store_matrix_sync(dst, c, 68, wmma::mem_row_major);
        }
        GBAR();

        // ---- epilogue: color = relu(p0+p1) * sigmoid(vis), group's 16 rows ----
        if (t2 < 48) {
            int pp = rowM + t2 / 3, c = t2 % 3;
            int gg = tile * 128 + pp;
            if (gg < N) {
                float v = colH[pp * 68 + c] + bufA[pp * 68 + 32 + c];
                out[3 * (size_t)gg + c] = fmaxf(v, 0.f) * visR[pp];
            }
        }
        GBAR();
    }
}

extern "C" void kernel_launch(void* const* d_in, const int* in_sizes, int n_in,
                              void* d_out, int out_size) {
    const float* x_feat = (const float*)d_in[0];
    const float* dv     = (const float*)d_in[1];
    const float* lv     = (const float*)d_in[2];
    const float* w_sig0 = (const float*)d_in[3];
    const float* w_sig1 = (const float*)d_in[4];
    const float* w_col0 = (const float*)d_in[5];
    const float* w_col1 = (const float*)d_in[6];
    const float* w_col2 = (const float*)d_in[7];
    const float* w_vis0 = (const float*)d_in[8];
    const float* w_vis1 = (const float*)d_in[9];
    float* out = (float*)d_out;
    int N = in_sizes[0] / 32;
    int ntiles = (N + 127) / 128;

    int dev = 0, smc = 148;
    cudaGetDevice(&dev);
    cudaDeviceGetAttribute(&smc, cudaDevAttrMultiProcessorCount, dev);
    int grid = (smc < ntiles) ? smc : ntiles;

    cudaFuncSetAttribute(nerf_wmma, cudaFuncAttributeMaxDynamicSharedMemorySize,
                         SMEM_BYTES);

    prep_kernel<<<1, 256>>>(w_sig0, w_sig1, w_col0, w_col1, w_col2, w_vis0, w_vis1);
    nerf_wmma<<<grid, 512, SMEM_BYTES>>>(x_feat, dv, lv, out, N, ntiles);
}

// round 12
// speedup vs baseline: 1.8772x; 1.8772x over previous
#include <cuda_runtime.h>
#include <cstdint>

// ---------------- weight layout: mma-fragment-packed blocks ----------------
// Each (ktile, npair) block = 128 floats: lane*4 + {b0_j0, b1_j0, b0_j1, b1_j1}
// b0 = B[kt*8 + (lane&3)][n], b1 = B[kt*8 + (lane&3)+4][n], n = np*16 + j*8 + (lane>>2)
#define OFF_COL0 0          // 8 kt x 4 np
#define OFF_VIS0 4096       // 6 x 4
#define OFF_SIG0 7168       // 4 x 4
#define OFF_C1A  9216       // 8 x 4
#define OFF_C1B  13312      // 2 x 4 (k row0 zero, rows1..15 = col1 rows 64..78)
#define OFF_SIG1 14336      // 8 x 1
#define OFF_VIS1 15360      // 8 x 1 (n==0 real)
#define OFF_COL2 16384      // 8 x 1 (n<3 real)
#define W_TOTAL  17408

__device__ __align__(16) float g_W[W_TOTAL];

__device__ __forceinline__ float tf32r(float x) {
    unsigned u;
    asm("cvt.rna.tf32.f32 %0, %1;" : "=r"(u) : "f"(x));
    return __uint_as_float(u);
}

__device__ void packB(float* dst, const float* W, int Kreal, int Nreal,
                      int KT, int NP, int t, int st) {
    for (int idx = t; idx < KT * NP * 128; idx += st) {
        int blk = idx >> 7, w = idx & 127;
        int lane = w >> 2, j = w & 3;
        int kt = blk / NP, np = blk % NP;
        int k = kt * 8 + (lane & 3) + ((j & 1) << 2);
        int n = np * 16 + ((j >> 1) << 3) + (lane >> 2);
        float v = (k < Kreal && n < Nreal) ? W[k * Nreal + n] : 0.f;
        dst[idx] = tf32r(v);
    }
}

__global__ void prep_kernel(const float* __restrict__ ws0, const float* __restrict__ ws1,
                            const float* __restrict__ wc0, const float* __restrict__ wc1,
                            const float* __restrict__ wc2, const float* __restrict__ wv0,
                            const float* __restrict__ wv1) {
    int t = threadIdx.x;
    packB(g_W + OFF_COL0, wc0, 64, 64, 8, 4, t, 256);
    packB(g_W + OFF_VIS0, wv0, 48, 64, 6, 4, t, 256);
    packB(g_W + OFF_SIG0, ws0, 32, 64, 4, 4, t, 256);
    packB(g_W + OFF_C1A,  wc1, 64, 64, 8, 4, t, 256);
    packB(g_W + OFF_SIG1, ws1, 64, 16, 8, 1, t, 256);
    packB(g_W + OFF_VIS1, wv1, 64, 1,  8, 1, t, 256);
    packB(g_W + OFF_COL2, wc2, 64, 3,  8, 1, t, 256);
    for (int idx = t; idx < 2 * 4 * 128; idx += 256) {   // C1B
        int blk = idx >> 7, w = idx & 127;
        int lane = w >> 2, j = w & 3;
        int kt = blk / 4, np = blk % 4;
        int k = kt * 8 + (lane & 3) + ((j & 1) << 2);
        int n = np * 16 + ((j >> 1) << 3) + (lane >> 2);
        float v = (k >= 1 && k < 16) ? wc1[(63 + k) * 64 + n] : 0.f;
        g_W[OFF_C1B + idx] = tf32r(v);
    }
}

// ---------------- SH degree-4 ----------------
__device__ __forceinline__ void sh16(float x, float y, float z, float* e) {
    float xx = x * x, yy = y * y, zz = z * z;
    float xy = x * y, yz = y * z, xz = x * z;
    e[0]  = 0.28209479177387814f;
    e[1]  = -0.48860251190291987f * y;
    e[2]  = 0.48860251190291987f * z;
    e[3]  = -0.48860251190291987f * x;
    e[4]  = 1.0925484305920792f * xy;
    e[5]  = -1.0925484305920792f * yz;
    e[6]  = 0.94617469575756f * zz - 0.31539156525252005f;
    e[7]  = -1.0925484305920792f * xz;
    e[8]  = 0.5462742152960396f * (xx - yy);
    e[9]  = 0.5900435899266435f * y * (3.0f * xx - yy);
    e[10] = 2.890611442640554f * xy * z;
    e[11] = 0.4570457994644657f * y * (4.0f * zz - xx - yy);
    e[12] = 0.3731763325901154f * z * (2.0f * zz - 3.0f * xx - 3.0f * yy);
    e[13] = 0.4570457994644657f * x * (4.0f * zz - xx - yy);
    e[14] = 1.445305721320277f * z * (xx - yy);
    e[15] = 0.5900435899266435f * x * (xx - 3.0f * yy);
}

// ---------------- smem layout (floats) ----------------
#define SM_BUFA  17408              // [128][68] inputs; geo cols 0..15; col2 partial cols 32..47
#define SM_SIGH  26112              // [128][68] sig_h; later col1_h
#define SM_VISH  34816              // [128][68] vis_h; later vis1
#define SM_COLH  43520              // [128][68] col0_h; later col2 partial
#define SM_VIS   52224              // [128]
#define SM_TOTAL 52352
#define SMEM_BYTES (SM_TOTAL * 4)

// ---------------- raw mma helpers ----------------
__device__ __forceinline__ void mma8(float* c, const unsigned* a, float bx, float by) {
    asm volatile(
        "mma.sync.aligned.m16n8k8.row.col.f32.tf32.tf32.f32 "
        "{%0,%1,%2,%3}, {%4,%5,%6,%7}, {%8,%9}, {%0,%1,%2,%3};"
        : "+f"(c[0]), "+f"(c[1]), "+f"(c[2]), "+f"(c[3])
        : "r"(a[0]), "r"(a[1]), "r"(a[2]), "r"(a[3]),
          "r"(__float_as_uint(bx)), "r"(__float_as_uint(by)));
}

// A fragment from row-major [.,68] buffer (Ab already + rowM*68)
__device__ __forceinline__ void loadA(unsigned* a, const float* Ab, int kt, int lane) {
    int r = lane >> 2, q = lane & 3;
    const float* p = Ab + r * 68 + kt * 8 + q;
    a[0] = __float_as_uint(p[0]);
    a[1] = __float_as_uint(p[8 * 68]);
    a[2] = __float_as_uint(p[4]);
    a[3] = __float_as_uint(p[8 * 68 + 4]);
}

__device__ __forceinline__ void storeFrag(float* dst, int rowM, int cbase, int lane,
                                          float c0, float c1, float c2, float c3) {
    int r = lane >> 2, q = lane & 3;
    *(float2*)(dst + (rowM + r) * 68 + cbase + 2 * q) = make_float2(c0, c1);
    *(float2*)(dst + (rowM + r + 8) * 68 + cbase + 2 * q) = make_float2(c2, c3);
}

// wide layer: KS ktiles, 2 npairs (p0, p0+1) -> 4 chains; relu+round store
template <int KS>
__device__ __forceinline__ void layerW(const unsigned a[][4], const float* B, int NP,
                                       int p0, float* dst, int rowM, int lane) {
    float c[4][4];
#pragma unroll
    for (int i = 0; i < 4; i++)
#pragma unroll
        for (int j = 0; j < 4; j++) c[i][j] = 0.f;
#pragma unroll
    for (int kt = 0; kt < KS; kt++) {
        float4 b0 = *(const float4*)(B + (kt * NP + p0) * 128 + lane * 4);
        float4 b1 = *(const float4*)(B + (kt * NP + p0 + 1) * 128 + lane * 4);
        mma8(c[0], a[kt], b0.x, b0.y);
        mma8(c[1], a[kt], b0.z, b0.w);
        mma8(c[2], a[kt], b1.x, b1.y);
        mma8(c[3], a[kt], b1.z, b1.w);
    }
#pragma unroll
    for (int f = 0; f < 4; f++)
        storeFrag(dst, rowM, p0 * 16 + f * 8, lane,
                  tf32r(fmaxf(c[f][0], 0.f)), tf32r(fmaxf(c[f][1], 0.f)),
                  tf32r(fmaxf(c[f][2], 0.f)), tf32r(fmaxf(c[f][3], 0.f)));
}

// group barrier: 128 threads (4 warps), barrier id g+1
#define GBAR() asm volatile("bar.sync %0, %1;" :: "r"(g + 1), "r"(128) : "memory")

__global__ void __launch_bounds__(512, 1)
nerf_mma(const float* __restrict__ x_feat, const float* __restrict__ dvec,
         const float* __restrict__ lvec, float* __restrict__ out,
         int N, int ntiles) {
    extern __shared__ float sm[];
    float* sW   = sm;
    float* bufA = sm + SM_BUFA;
    float* sigH = sm + SM_SIGH;
    float* visH = sm + SM_VISH;
    float* colH = sm + SM_COLH;
    float* visR = sm + SM_VIS;

    int tid = threadIdx.x, wid = tid >> 5, lane = tid & 31;
    int g = wid >> 2;               // 4 groups of 4 warps, 32 rows each
    int w4 = wid & 3;
    int blk = w4 >> 1, h = w4 & 1;
    int rowM = g * 32 + blk * 16;   // warp's 16-row block
    int p0 = 2 * h;                 // warp's first npair (2 npairs = 32 cols)
    int t2 = tid & 127;

    {
        const float4* s = (const float4*)g_W;
        float4* d = (float4*)sW;
        for (int i = tid; i < W_TOTAL / 4; i += 512) d[i] = s[i];
    }
    __syncthreads();

    for (int tile = blockIdx.x; tile < ntiles; tile += gridDim.x) {
        // ---- phase 0: group fills its 32 rows of bufA ----
        {
            int r = g * 32 + (t2 & 31);
            int p = tile * 128 + r;
            int pc = (p < N) ? p : (N - 1);
            if (t2 < 32) {
                const float4* xp = (const float4*)(x_feat + 32 * (size_t)pc);
                float* dst = bufA + r * 68;
#pragma unroll
                for (int i = 0; i < 8; i++) {
                    float4 v = xp[i];
                    dst[4 * i]     = tf32r(v.x);
                    dst[4 * i + 1] = tf32r(v.y);
                    dst[4 * i + 2] = tf32r(v.z);
                    dst[4 * i + 3] = tf32r(v.w);
                }
            } else if (t2 < 64) {
                float e[16];
                const float* lp = lvec + 3 * (size_t)pc;
                sh16(lp[0], lp[1], lp[2], e);
                float* dst = bufA + r * 68 + 32;
#pragma unroll
                for (int i = 0; i < 16; i++) dst[i] = tf32r(e[i]);
            } else if (t2 < 96) {
                float e[16];
                const float* dp = dvec + 3 * (size_t)pc;
                sh16(dp[0], dp[1], dp[2], e);
                float* dst = bufA + r * 68 + 48;
#pragma unroll
                for (int i = 0; i < 16; i++) dst[i] = tf32r(e[i]);
            }
        }
        GBAR();

        // ---- phase 1: A hoisted once; sig0/vis0/col0, 4 chains each ----
        {
            unsigned a[8][4];
#pragma unroll
            for (int kt = 0; kt < 8; kt++) loadA(a[kt], bufA + rowM * 68, kt, lane);
            layerW<4>(a, sW + OFF_SIG0, 4, p0, sigH, rowM, lane);
            layerW<6>(a, sW + OFF_VIS0, 4, p0, visH, rowM, lane);
            layerW<8>(a, sW + OFF_COL0, 4, p0, colH, rowM, lane);
        }
        GBAR();

        // ---- phase 2: h==0 -> sig1 (geo -> bufA 0..15); h==1 -> vis1 ----
        {
            const float* Ain = (h ? visH : sigH) + rowM * 68;
            const float* Bw = h ? (sW + OFF_VIS1) : (sW + OFF_SIG1);
            unsigned a[8][4];
#pragma unroll
            for (int kt = 0; kt < 8; kt++) loadA(a[kt], Ain, kt, lane);
            float c[2][4];
#pragma unroll
            for (int i = 0; i < 2; i++)
#pragma unroll
                for (int j = 0; j < 4; j++) c[i][j] = 0.f;
#pragma unroll
            for (int kt = 0; kt < 8; kt++) {
                float4 b = *(const float4*)(Bw + kt * 128 + lane * 4);
                mma8(c[0], a[kt], b.x, b.y);
                mma8(c[1], a[kt], b.z, b.w);
            }
            if (h == 0) {   // geo: round, NO relu
#pragma unroll
                for (int f = 0; f < 2; f++)
                    storeFrag(bufA, rowM, f * 8, lane,
                              tf32r(c[f][0]), tf32r(c[f][1]), tf32r(c[f][2]), tf32r(c[f][3]));
            } else {        // vis raw logit (col 0 real)
#pragma unroll
                for (int f = 0; f < 2; f++)
                    storeFrag(visH, rowM, f * 8, lane,
                              c[f][0], c[f][1], c[f][2], c[f][3]);
            }
        }
        GBAR();
        if (t2 < 32) {
            int r = g * 32 + t2;
            visR[r] = __fdividef(1.f, 1.f + __expf(-visH[r * 68]));
        }

        // ---- phase 3: col1 = relu(col0_h @ C1A + geo @ C1B), 4 chains -> sigH
        {
            unsigned a1[8][4], ag[2][4];
#pragma unroll
            for (int kt = 0; kt < 8; kt++) loadA(a1[kt], colH + rowM * 68, kt, lane);
#pragma unroll
            for (int kt = 0; kt < 2; kt++) loadA(ag[kt], bufA + rowM * 68, kt, lane);
            float c[4][4];
#pragma unroll
            for (int i = 0; i < 4; i++)
#pragma unroll
                for (int j = 0; j < 4; j++) c[i][j] = 0.f;
#pragma unroll
            for (int kt = 0; kt < 8; kt++) {
                float4 b0 = *(const float4*)(sW + OFF_C1A + (kt * 4 + p0) * 128 + lane * 4);
                float4 b1 = *(const float4*)(sW + OFF_C1A + (kt * 4 + p0 + 1) * 128 + lane * 4);
                mma8(c[0], a1[kt], b0.x, b0.y);
                mma8(c[1], a1[kt], b0.z, b0.w);
                mma8(c[2], a1[kt], b1.x, b1.y);
                mma8(c[3], a1[kt], b1.z, b1.w);
            }
#pragma unroll
            for (int kt = 0; kt < 2; kt++) {
                float4 b0 = *(const float4*)(sW + OFF_C1B + (kt * 4 + p0) * 128 + lane * 4);
                float4 b1 = *(const float4*)(sW + OFF_C1B + (kt * 4 + p0 + 1) * 128 + lane * 4);
                mma8(c[0], ag[kt], b0.x, b0.y);
                mma8(c[1], ag[kt], b0.z, b0.w);
                mma8(c[2], ag[kt], b1.x, b1.y);
                mma8(c[3], ag[kt], b1.z, b1.w);
            }
#pragma unroll
            for (int f = 0; f < 4; f++)
                storeFrag(sigH, rowM, p0 * 16 + f * 8, lane,
                          tf32r(fmaxf(c[f][0], 0.f)), tf32r(fmaxf(c[f][1], 0.f)),
                          tf32r(fmaxf(c[f][2], 0.f)), tf32r(fmaxf(c[f][3], 0.f)));
        }
        GBAR();

        // ---- phase 4: col2, split-k across h: h==0 kt0..3 -> colH; h==1 kt4..7 -> bufA+32
        {
            unsigned a[4][4];
#pragma unroll
            for (int kt = 0; kt < 4; kt++) loadA(a[kt], sigH + rowM * 68, h * 4 + kt, lane);
            float c[2][4];
#pragma unroll
            for (int i = 0; i < 2; i++)
#pragma unroll
                for (int j = 0; j < 4; j++) c[i][j] = 0.f;
#pragma unroll
            for (int kt = 0; kt < 4; kt++) {
                float4 b = *(const float4*)(sW + OFF_COL2 + (h * 4 + kt) * 128 + lane * 4);
                mma8(c[0], a[kt], b.x, b.y);
                mma8(c[1], a[kt], b.z, b.w);
            }
            float* dst = h ? bufA : colH;
            int cb = h ? 32 : 0;
#pragma unroll
            for (int f = 0; f < 2; f++)
                storeFrag(dst, rowM, cb + f * 8, lane,
                          c[f][0], c[f][1], c[f][2], c[f][3]);
        }
        GBAR();

        // ---- epilogue: color = relu(p0+p1) * sigmoid(vis), group's 32 rows ----
        for (int i = t2; i < 96; i += 128) {
            int pp = g * 32 + i / 3, c = i % 3;
            int gg = tile * 128 + pp;
            if (gg < N) {
                float v = colH[pp * 68 + c] + bufA[pp * 68 + 32 + c];
                out[3 * (size_t)gg + c] = fmaxf(v, 0.f) * visR[pp];
            }
        }
        GBAR();
    }
}

extern "C" void kernel_launch(void* const* d_in, const int* in_sizes, int n_in,
                              void* d_out, int out_size) {
    const float* x_feat = (const float*)d_in[0];
    const float* dv     = (const float*)d_in[1];
    const float* lv     = (const float*)d_in[2];
    const float* w_sig0 = (const float*)d_in[3];
    const float* w_sig1 = (const float*)d_in[4];
    const float* w_col0 = (const float*)d_in[5];
    const float* w_col1 = (const float*)d_in[6];
    const float* w_col2 = (const float*)d_in[7];
    const float* w_vis0 = (const float*)d_in[8];
    const float* w_vis1 = (const float*)d_in[9];
    float* out = (float*)d_out;
    int N = in_sizes[0] / 32;
    int ntiles = (N + 127) / 128;

    int dev = 0, smc = 148;
    cudaGetDevice(&dev);
    cudaDeviceGetAttribute(&smc, cudaDevAttrMultiProcessorCount, dev);
    int grid = (smc < ntiles) ? smc : ntiles;

    cudaFuncSetAttribute(nerf_mma, cudaFuncAttributeMaxDynamicSharedMemorySize,
                         SMEM_BYTES);

    prep_kernel<<<1, 256>>>(w_sig0, w_sig1, w_col0, w_col1, w_col2, w_vis0, w_vis1);
    nerf_mma<<<grid, 512, SMEM_BYTES>>>(x_feat, dv, lv, out, N, ntiles);
}

// round 13
// speedup vs baseline: 1.9786x; 1.0540x over previous
#include <cuda_runtime.h>
#include <cstdint>

// ---------------- weight layout: mma-fragment-packed blocks ----------------
// Each (ktile, npair) block = 128 floats: lane*4 + {b0_j0, b1_j0, b0_j1, b1_j1}
// b0 = B[kt*8 + (lane&3)][n], b1 = B[kt*8 + (lane&3)+4][n], n = np*16 + j*8 + (lane>>2)
#define OFF_COL0 0          // 8 kt x 4 np
#define OFF_VIS0 4096       // 6 x 4
#define OFF_SIG0 7168       // 4 x 4
#define OFF_C1A  9216       // 8 x 4
#define OFF_C1B  13312      // 2 x 4 (k row0 zero, rows1..15 = col1 rows 64..78)
#define OFF_SIG1 14336      // 8 x 1
#define OFF_VIS1 15360      // 8 x 1 (n==0 real)
#define OFF_COL2 16384      // 8 x 1 (n<3 real)
#define W_TOTAL  17408

__device__ __align__(16) float g_W[W_TOTAL];

__device__ __forceinline__ float tf32r(float x) {
    unsigned u;
    asm("cvt.rna.tf32.f32 %0, %1;" : "=r"(u) : "f"(x));
    return __uint_as_float(u);
}

__device__ void packB(float* dst, const float* W, int Kreal, int Nreal,
                      int KT, int NP, int t, int st) {
    for (int idx = t; idx < KT * NP * 128; idx += st) {
        int blk = idx >> 7, w = idx & 127;
        int lane = w >> 2, j = w & 3;
        int kt = blk / NP, np = blk % NP;
        int k = kt * 8 + (lane & 3) + ((j & 1) << 2);
        int n = np * 16 + ((j >> 1) << 3) + (lane >> 2);
        float v = (k < Kreal && n < Nreal) ? W[k * Nreal + n] : 0.f;
        dst[idx] = tf32r(v);
    }
}

__global__ void prep_kernel(const float* __restrict__ ws0, const float* __restrict__ ws1,
                            const float* __restrict__ wc0, const float* __restrict__ wc1,
                            const float* __restrict__ wc2, const float* __restrict__ wv0,
                            const float* __restrict__ wv1) {
    int t = threadIdx.x;
    packB(g_W + OFF_COL0, wc0, 64, 64, 8, 4, t, 256);
    packB(g_W + OFF_VIS0, wv0, 48, 64, 6, 4, t, 256);
    packB(g_W + OFF_SIG0, ws0, 32, 64, 4, 4, t, 256);
    packB(g_W + OFF_C1A,  wc1, 64, 64, 8, 4, t, 256);
    packB(g_W + OFF_SIG1, ws1, 64, 16, 8, 1, t, 256);
    packB(g_W + OFF_VIS1, wv1, 64, 1,  8, 1, t, 256);
    packB(g_W + OFF_COL2, wc2, 64, 3,  8, 1, t, 256);
    for (int idx = t; idx < 2 * 4 * 128; idx += 256) {   // C1B
        int blk = idx >> 7, w = idx & 127;
        int lane = w >> 2, j = w & 3;
        int kt = blk / 4, np = blk % 4;
        int k = kt * 8 + (lane & 3) + ((j & 1) << 2);
        int n = np * 16 + ((j >> 1) << 3) + (lane >> 2);
        float v = (k >= 1 && k < 16) ? wc1[(63 + k) * 64 + n] : 0.f;
        g_W[OFF_C1B + idx] = tf32r(v);
    }
}

// ---------------- SH degree-4 ----------------
__device__ __forceinline__ void sh16(float x, float y, float z, float* e) {
    float xx = x * x, yy = y * y, zz = z * z;
    float xy = x * y, yz = y * z, xz = x * z;
    e[0]  = 0.28209479177387814f;
    e[1]  = -0.48860251190291987f * y;
    e[2]  = 0.48860251190291987f * z;
    e[3]  = -0.48860251190291987f * x;
    e[4]  = 1.0925484305920792f * xy;
    e[5]  = -1.0925484305920792f * yz;
    e[6]  = 0.94617469575756f * zz - 0.31539156525252005f;
    e[7]  = -1.0925484305920792f * xz;
    e[8]  = 0.5462742152960396f * (xx - yy);
    e[9]  = 0.5900435899266435f * y * (3.0f * xx - yy);
    e[10] = 2.890611442640554f * xy * z;
    e[11] = 0.4570457994644657f * y * (4.0f * zz - xx - yy);
    e[12] = 0.3731763325901154f * z * (2.0f * zz - 3.0f * xx - 3.0f * yy);
    e[13] = 0.4570457994644657f * x * (4.0f * zz - xx - yy);
    e[14] = 1.445305721320277f * z * (xx - yy);
    e[15] = 0.5900435899266435f * x * (xx - 3.0f * yy);
}

// ---------------- smem layout (floats) ----------------
#define SM_BUFA  17408              // [128][68] inputs; geo cols 0..15; col2 partial cols 32..47
#define SM_SIGH  26112              // [128][68] sig_h; later col1_h
#define SM_VISH  34816              // [128][68] vis_h; later vis1
#define SM_COLH  43520              // [128][68] col0_h; later col2 partial
#define SM_VIS   52224              // [128]
#define SM_TOTAL 52352
#define SMEM_BYTES (SM_TOTAL * 4)

// ---------------- raw mma helpers ----------------
__device__ __forceinline__ void mma8(float* c, const unsigned* a, float bx, float by) {
    asm volatile(
        "mma.sync.aligned.m16n8k8.row.col.f32.tf32.tf32.f32 "
        "{%0,%1,%2,%3}, {%4,%5,%6,%7}, {%8,%9}, {%0,%1,%2,%3};"
        : "+f"(c[0]), "+f"(c[1]), "+f"(c[2]), "+f"(c[3])
        : "r"(a[0]), "r"(a[1]), "r"(a[2]), "r"(a[3]),
          "r"(__float_as_uint(bx)), "r"(__float_as_uint(by)));
}

// A fragment from row-major [.,68] buffer (Ab already + row0*68)
__device__ __forceinline__ void loadA(unsigned* a, const float* Ab, int kt, int lane) {
    int r = lane >> 2, q = lane & 3;
    const float* p = Ab + r * 68 + kt * 8 + q;
    a[0] = __float_as_uint(p[0]);
    a[1] = __float_as_uint(p[8 * 68]);
    a[2] = __float_as_uint(p[4]);
    a[3] = __float_as_uint(p[8 * 68 + 4]);
}

__device__ __forceinline__ void storeFrag(float* dst, int row0, int cbase, int lane,
                                          float c0, float c1, float c2, float c3) {
    int r = lane >> 2, q = lane & 3;
    *(float2*)(dst + (row0 + r) * 68 + cbase + 2 * q) = make_float2(c0, c1);
    *(float2*)(dst + (row0 + r + 8) * 68 + cbase + 2 * q) = make_float2(c2, c3);
}

// wide layer: KS ktiles, 1 npair, TWO m-blocks sharing each B load (4 chains)
template <int KS>
__device__ __forceinline__ void layer2m(const unsigned a0[][4], const unsigned a1[][4],
                                        const float* B, int np, float* dst,
                                        int rowM, int lane) {
    float c[4][4];
#pragma unroll
    for (int i = 0; i < 4; i++)
#pragma unroll
        for (int j = 0; j < 4; j++) c[i][j] = 0.f;
#pragma unroll
    for (int kt = 0; kt < KS; kt++) {
        float4 b = *(const float4*)(B + (kt * 4 + np) * 128 + lane * 4);
        mma8(c[0], a0[kt], b.x, b.y);
        mma8(c[1], a0[kt], b.z, b.w);
        mma8(c[2], a1[kt], b.x, b.y);
        mma8(c[3], a1[kt], b.z, b.w);
    }
    storeFrag(dst, rowM, np * 16, lane,
              tf32r(fmaxf(c[0][0], 0.f)), tf32r(fmaxf(c[0][1], 0.f)),
              tf32r(fmaxf(c[0][2], 0.f)), tf32r(fmaxf(c[0][3], 0.f)));
    storeFrag(dst, rowM, np * 16 + 8, lane,
              tf32r(fmaxf(c[1][0], 0.f)), tf32r(fmaxf(c[1][1], 0.f)),
              tf32r(fmaxf(c[1][2], 0.f)), tf32r(fmaxf(c[1][3], 0.f)));
    storeFrag(dst, rowM + 16, np * 16, lane,
              tf32r(fmaxf(c[2][0], 0.f)), tf32r(fmaxf(c[2][1], 0.f)),
              tf32r(fmaxf(c[2][2], 0.f)), tf32r(fmaxf(c[2][3], 0.f)));
    storeFrag(dst, rowM + 16, np * 16 + 8, lane,
              tf32r(fmaxf(c[3][0], 0.f)), tf32r(fmaxf(c[3][1], 0.f)),
              tf32r(fmaxf(c[3][2], 0.f)), tf32r(fmaxf(c[3][3], 0.f)));
}

// group barrier: 128 threads (4 warps), barrier id g+1
#define GBAR() asm volatile("bar.sync %0, %1;" :: "r"(g + 1), "r"(128) : "memory")

__global__ void __launch_bounds__(512, 1)
nerf_mma(const float* __restrict__ x_feat, const float* __restrict__ dvec,
         const float* __restrict__ lvec, float* __restrict__ out,
         int N, int ntiles) {
    extern __shared__ float sm[];
    float* sW   = sm;
    float* bufA = sm + SM_BUFA;
    float* sigH = sm + SM_SIGH;
    float* visH = sm + SM_VISH;
    float* colH = sm + SM_COLH;
    float* visR = sm + SM_VIS;

    int tid = threadIdx.x, wid = tid >> 5, lane = tid & 31;
    int g = wid >> 2;               // 4 groups of 4 warps, 32 rows each
    int np = wid & 3;               // warp's npair (16 cols) in phases 1/3
    int rowM = g * 32;              // group's (and warp's) 32-row stripe
    // phase 2/4 mapping within group
    int sub = np & 1, which = np >> 1;
    int rowW = rowM + sub * 16;
    int t2 = tid & 127;

    {
        const float4* s = (const float4*)g_W;
        float4* d = (float4*)sW;
        for (int i = tid; i < W_TOTAL / 4; i += 512) d[i] = s[i];
    }
    __syncthreads();

    for (int tile = blockIdx.x; tile < ntiles; tile += gridDim.x) {
        // ---- phase 0: group fills its 32 rows of bufA ----
        {
            int r = rowM + (t2 & 31);
            int p = tile * 128 + r;
            int pc = (p < N) ? p : (N - 1);
            if (t2 < 32) {
                const float4* xp = (const float4*)(x_feat + 32 * (size_t)pc);
                float* dst = bufA + r * 68;
#pragma unroll
                for (int i = 0; i < 8; i++) {
                    float4 v = xp[i];
                    dst[4 * i]     = tf32r(v.x);
                    dst[4 * i + 1] = tf32r(v.y);
                    dst[4 * i + 2] = tf32r(v.z);
                    dst[4 * i + 3] = tf32r(v.w);
                }
            } else if (t2 < 64) {
                float e[16];
                const float* lp = lvec + 3 * (size_t)pc;
                sh16(lp[0], lp[1], lp[2], e);
                float* dst = bufA + r * 68 + 32;
#pragma unroll
                for (int i = 0; i < 16; i++) dst[i] = tf32r(e[i]);
            } else if (t2 < 96) {
                float e[16];
                const float* dp = dvec + 3 * (size_t)pc;
                sh16(dp[0], dp[1], dp[2], e);
                float* dst = bufA + r * 68 + 48;
#pragma unroll
                for (int i = 0; i < 16; i++) dst[i] = tf32r(e[i]);
            }
        }
        GBAR();

        // ---- phase 1: A hoisted for BOTH m-blocks; B loaded once per kt ----
        {
            unsigned a0[8][4], a1[8][4];
#pragma unroll
            for (int kt = 0; kt < 8; kt++) {
                loadA(a0[kt], bufA + rowM * 68, kt, lane);
                loadA(a1[kt], bufA + (rowM + 16) * 68, kt, lane);
            }
            layer2m<4>(a0, a1, sW + OFF_SIG0, np, sigH, rowM, lane);
            layer2m<6>(a0, a1, sW + OFF_VIS0, np, visH, rowM, lane);
            layer2m<8>(a0, a1, sW + OFF_COL0, np, colH, rowM, lane);
        }
        GBAR();

        // ---- phase 2: which==0 -> sig1 (geo -> bufA 0..15); which==1 -> vis1
        {
            const float* Ain = (which ? visH : sigH) + rowW * 68;
            unsigned a[8][4];
#pragma unroll
            for (int kt = 0; kt < 8; kt++) loadA(a[kt], Ain, kt, lane);
            if (which == 0) {       // sig1: 16 cols
                float c0[4] = {0.f, 0.f, 0.f, 0.f}, c1[4] = {0.f, 0.f, 0.f, 0.f};
#pragma unroll
                for (int kt = 0; kt < 8; kt++) {
                    float4 b = *(const float4*)(sW + OFF_SIG1 + kt * 128 + lane * 4);
                    mma8(c0, a[kt], b.x, b.y);
                    mma8(c1, a[kt], b.z, b.w);
                }
                // geo: round, NO relu
                storeFrag(bufA, rowW, 0, lane,
                          tf32r(c0[0]), tf32r(c0[1]), tf32r(c0[2]), tf32r(c0[3]));
                storeFrag(bufA, rowW, 8, lane,
                          tf32r(c1[0]), tf32r(c1[1]), tf32r(c1[2]), tf32r(c1[3]));
            } else {                // vis1: 1 real col -> single n8 frag
                float c0[4] = {0.f, 0.f, 0.f, 0.f};
#pragma unroll
                for (int kt = 0; kt < 8; kt++) {
                    float2 b = *(const float2*)(sW + OFF_VIS1 + kt * 128 + lane * 4);
                    mma8(c0, a[kt], b.x, b.y);
                }
                storeFrag(visH, rowW, 0, lane, c0[0], c0[1], c0[2], c0[3]);
            }
        }
        GBAR();
        if (t2 < 32) {
            int r = rowM + t2;
            visR[r] = __fdividef(1.f, 1.f + __expf(-visH[r * 68]));
        }

        // ---- phase 3: col1 = relu(col0_h @ C1A + geo @ C1B), 2 m-blocks, 1 npair
        {
            unsigned a0[8][4], a1[8][4], g0[2][4], g1[2][4];
#pragma unroll
            for (int kt = 0; kt < 8; kt++) {
                loadA(a0[kt], colH + rowM * 68, kt, lane);
                loadA(a1[kt], colH + (rowM + 16) * 68, kt, lane);
            }
#pragma unroll
            for (int kt = 0; kt < 2; kt++) {
                loadA(g0[kt], bufA + rowM * 68, kt, lane);
                loadA(g1[kt], bufA + (rowM + 16) * 68, kt, lane);
            }
            float c[4][4];
#pragma unroll
            for (int i = 0; i < 4; i++)
#pragma unroll
                for (int j = 0; j < 4; j++) c[i][j] = 0.f;
#pragma unroll
            for (int kt = 0; kt < 8; kt++) {
                float4 b = *(const float4*)(sW + OFF_C1A + (kt * 4 + np) * 128 + lane * 4);
                mma8(c[0], a0[kt], b.x, b.y);
                mma8(c[1], a0[kt], b.z, b.w);
                mma8(c[2], a1[kt], b.x, b.y);
                mma8(c[3], a1[kt], b.z, b.w);
            }
#pragma unroll
            for (int kt = 0; kt < 2; kt++) {
                float4 b = *(const float4*)(sW + OFF_C1B + (kt * 4 + np) * 128 + lane * 4);
                mma8(c[0], g0[kt], b.x, b.y);
                mma8(c[1], g0[kt], b.z, b.w);
                mma8(c[2], g1[kt], b.x, b.y);
                mma8(c[3], g1[kt], b.z, b.w);
            }
            storeFrag(sigH, rowM, np * 16, lane,
                      tf32r(fmaxf(c[0][0], 0.f)), tf32r(fmaxf(c[0][1], 0.f)),
                      tf32r(fmaxf(c[0][2], 0.f)), tf32r(fmaxf(c[0][3], 0.f)));
            storeFrag(sigH, rowM, np * 16 + 8, lane,
                      tf32r(fmaxf(c[1][0], 0.f)), tf32r(fmaxf(c[1][1], 0.f)),
                      tf32r(fmaxf(c[1][2], 0.f)), tf32r(fmaxf(c[1][3], 0.f)));
            storeFrag(sigH, rowM + 16, np * 16, lane,
                      tf32r(fmaxf(c[2][0], 0.f)), tf32r(fmaxf(c[2][1], 0.f)),
                      tf32r(fmaxf(c[2][2], 0.f)), tf32r(fmaxf(c[2][3], 0.f)));
            storeFrag(sigH, rowM + 16, np * 16 + 8, lane,
                      tf32r(fmaxf(c[3][0], 0.f)), tf32r(fmaxf(c[3][1], 0.f)),
                      tf32r(fmaxf(c[3][2], 0.f)), tf32r(fmaxf(c[3][3], 0.f)));
        }
        GBAR();

        // ---- phase 4: col2 (3 real cols): sub = m-block, which = k-half ----
        {
            unsigned a[4][4];
#pragma unroll
            for (int kt = 0; kt < 4; kt++)
                loadA(a[kt], sigH + rowW * 68, which * 4 + kt, lane);
            float c0[4] = {0.f, 0.f, 0.f, 0.f};
#pragma unroll
            for (int kt = 0; kt < 4; kt++) {
                float2 b = *(const float2*)(sW + OFF_COL2 + (which * 4 + kt) * 128 + lane * 4);
                mma8(c0, a[kt], b.x, b.y);
            }
            float* dst = which ? bufA : colH;
            int cb = which ? 32 : 0;
            storeFrag(dst, rowW, cb, lane, c0[0], c0[1], c0[2], c0[3]);
        }
        GBAR();

        // ---- epilogue: color = relu(p0+p1) * sigmoid(vis), group's 32 rows ----
        for (int i = t2; i < 96; i += 128) {
            int pp = rowM + i / 3, c = i % 3;
            int gg = tile * 128 + pp;
            if (gg < N) {
                float v = colH[pp * 68 + c] + bufA[pp * 68 + 32 + c];
                out[3 * (size_t)gg + c] = fmaxf(v, 0.f) * visR[pp];
            }
        }
        GBAR();
    }
}

extern "C" void kernel_launch(void* const* d_in, const int* in_sizes, int n_in,
                              void* d_out, int out_size) {
    const float* x_feat = (const float*)d_in[0];
    const float* dv     = (const float*)d_in[1];
    const float* lv     = (const float*)d_in[2];
    const float* w_sig0 = (const float*)d_in[3];
    const float* w_sig1 = (const float*)d_in[4];
    const float* w_col0 = (const float*)d_in[5];
    const float* w_col1 = (const float*)d_in[6];
    const float* w_col2 = (const float*)d_in[7];
    const float* w_vis0 = (const float*)d_in[8];
    const float* w_vis1 = (const float*)d_in[9];
    float* out = (float*)d_out;
    int N = in_sizes[0] / 32;
    int ntiles = (N + 127) / 128;

    int dev = 0, smc = 148;
    cudaGetDevice(&dev);
    cudaDeviceGetAttribute(&smc, cudaDevAttrMultiProcessorCount, dev);
    int grid = (smc < ntiles) ? smc : ntiles;

    cudaFuncSetAttribute(nerf_mma, cudaFuncAttributeMaxDynamicSharedMemorySize,
                         SMEM_BYTES);

    prep_kernel<<<1, 256>>>(w_sig0, w_sig1, w_col0, w_col1, w_col2, w_vis0, w_vis1);
    nerf_mma<<<grid, 512, SMEM_BYTES>>>(x_feat, dv, lv, out, N, ntiles);
}

// round 14
// speedup vs baseline: 2.3377x; 1.1815x over previous
#include <cuda_runtime.h>
#include <cstdint>

// ---------------- weight layout: mma-fragment-packed blocks ----------------
// Each (ktile, npair) block = 128 floats: lane*4 + {b0_j0, b1_j0, b0_j1, b1_j1}
#define OFF_COL0 0          // 8 kt x 4 np
#define OFF_VIS0 4096       // 6 x 4
#define OFF_SIG0 7168       // 4 x 4
#define OFF_C1A  9216       // 8 x 4
#define OFF_C1B  13312      // 2 x 4 (k row0 zero, rows1..15 = col1 rows 64..78)
#define OFF_SIG1 14336      // 8 x 1
#define OFF_V1L  15360      // 64 linear floats (vis1 weights) + pad
#define OFF_COL2 16384      // 8 x 1 (n<3 real)
#define W_TOTAL  17408

__device__ __align__(16) float g_W[W_TOTAL];

__device__ __forceinline__ float tf32r(float x) {
    unsigned u;
    asm("cvt.rna.tf32.f32 %0, %1;" : "=r"(u) : "f"(x));
    return __uint_as_float(u);
}

__device__ void packB(float* dst, const float* W, int Kreal, int Nreal,
                      int KT, int NP, int t, int st) {
    for (int idx = t; idx < KT * NP * 128; idx += st) {
        int blk = idx >> 7, w = idx & 127;
        int lane = w >> 2, j = w & 3;
        int kt = blk / NP, np = blk % NP;
        int k = kt * 8 + (lane & 3) + ((j & 1) << 2);
        int n = np * 16 + ((j >> 1) << 3) + (lane >> 2);
        float v = (k < Kreal && n < Nreal) ? W[k * Nreal + n] : 0.f;
        dst[idx] = tf32r(v);
    }
}

__global__ void prep_kernel(const float* __restrict__ ws0, const float* __restrict__ ws1,
                            const float* __restrict__ wc0, const float* __restrict__ wc1,
                            const float* __restrict__ wc2, const float* __restrict__ wv0,
                            const float* __restrict__ wv1) {
    int t = threadIdx.x;
    packB(g_W + OFF_COL0, wc0, 64, 64, 8, 4, t, 256);
    packB(g_W + OFF_VIS0, wv0, 48, 64, 6, 4, t, 256);
    packB(g_W + OFF_SIG0, ws0, 32, 64, 4, 4, t, 256);
    packB(g_W + OFF_C1A,  wc1, 64, 64, 8, 4, t, 256);
    packB(g_W + OFF_SIG1, ws1, 64, 16, 8, 1, t, 256);
    packB(g_W + OFF_COL2, wc2, 64, 3,  8, 1, t, 256);
    for (int i = t; i < 1024; i += 256)
        g_W[OFF_V1L + i] = (i < 64) ? tf32r(wv1[i]) : 0.f;
    for (int idx = t; idx < 2 * 4 * 128; idx += 256) {   // C1B
        int blk = idx >> 7, w = idx & 127;
        int lane = w >> 2, j = w & 3;
        int kt = blk / 4, np = blk % 4;
        int k = kt * 8 + (lane & 3) + ((j & 1) << 2);
        int n = np * 16 + ((j >> 1) << 3) + (lane >> 2);
        float v = (k >= 1 && k < 16) ? wc1[(63 + k) * 64 + n] : 0.f;
        g_W[OFF_C1B + idx] = tf32r(v);
    }
}

// ---------------- SH degree-4 ----------------
__device__ __forceinline__ void sh16(float x, float y, float z, float* e) {
    float xx = x * x, yy = y * y, zz = z * z;
    float xy = x * y, yz = y * z, xz = x * z;
    e[0]  = 0.28209479177387814f;
    e[1]  = -0.48860251190291987f * y;
    e[2]  = 0.48860251190291987f * z;
    e[3]  = -0.48860251190291987f * x;
    e[4]  = 1.0925484305920792f * xy;
    e[5]  = -1.0925484305920792f * yz;
    e[6]  = 0.94617469575756f * zz - 0.31539156525252005f;
    e[7]  = -1.0925484305920792f * xz;
    e[8]  = 0.5462742152960396f * (xx - yy);
    e[9]  = 0.5900435899266435f * y * (3.0f * xx - yy);
    e[10] = 2.890611442640554f * xy * z;
    e[11] = 0.4570457994644657f * y * (4.0f * zz - xx - yy);
    e[12] = 0.3731763325901154f * z * (2.0f * zz - 3.0f * xx - 3.0f * yy);
    e[13] = 0.4570457994644657f * x * (4.0f * zz - xx - yy);
    e[14] = 1.445305721320277f * z * (xx - yy);
    e[15] = 0.5900435899266435f * x * (xx - 3.0f * yy);
}

// ---------------- smem layout (floats): 256-row tile, TWO row-buffers ------
#define SM_B1    17408              // [256][68] inputs -> col0_h -> col2 partials
#define SM_B2    34816              // [256][68] sig_h -> geo(cols0..15) -> col1_h
#define SM_VISP  52224              // [256][2] vis partials
#define SM_VISR  52736              // [256]
#define SM_TOTAL 52992
#define SMEM_BYTES (SM_TOTAL * 4)

// ---------------- raw mma helpers ----------------
__device__ __forceinline__ void mma8(float* c, const unsigned* a, float bx, float by) {
    asm volatile(
        "mma.sync.aligned.m16n8k8.row.col.f32.tf32.tf32.f32 "
        "{%0,%1,%2,%3}, {%4,%5,%6,%7}, {%8,%9}, {%0,%1,%2,%3};"
        : "+f"(c[0]), "+f"(c[1]), "+f"(c[2]), "+f"(c[3])
        : "r"(a[0]), "r"(a[1]), "r"(a[2]), "r"(a[3]),
          "r"(__float_as_uint(bx)), "r"(__float_as_uint(by)));
}

__device__ __forceinline__ void loadA(unsigned* a, const float* Ab, int kt, int lane) {
    int r = lane >> 2, q = lane & 3;
    const float* p = Ab + r * 68 + kt * 8 + q;
    a[0] = __float_as_uint(p[0]);
    a[1] = __float_as_uint(p[8 * 68]);
    a[2] = __float_as_uint(p[4]);
    a[3] = __float_as_uint(p[8 * 68 + 4]);
}

__device__ __forceinline__ void storeFrag(float* dst, int row0, int cbase, int lane,
                                          float c0, float c1, float c2, float c3) {
    int r = lane >> 2, q = lane & 3;
    *(float2*)(dst + (row0 + r) * 68 + cbase + 2 * q) = make_float2(c0, c1);
    *(float2*)(dst + (row0 + r + 8) * 68 + cbase + 2 * q) = make_float2(c2, c3);
}

// one layer, one npair, TWO m-blocks sharing each B load; relu+round store
template <int KS>
__device__ __forceinline__ void layer2m(const unsigned a0[][4], const unsigned a1[][4],
                                        const float* B, int np, float* dst,
                                        int rowM, int lane) {
    float c[4][4];
#pragma unroll
    for (int i = 0; i < 4; i++)
#pragma unroll
        for (int j = 0; j < 4; j++) c[i][j] = 0.f;
#pragma unroll
    for (int kt = 0; kt < KS; kt++) {
        float4 b = *(const float4*)(B + (kt * 4 + np) * 128 + lane * 4);
        mma8(c[0], a0[kt], b.x, b.y);
        mma8(c[1], a0[kt], b.z, b.w);
        mma8(c[2], a1[kt], b.x, b.y);
        mma8(c[3], a1[kt], b.z, b.w);
    }
    storeFrag(dst, rowM, np * 16, lane,
              tf32r(fmaxf(c[0][0], 0.f)), tf32r(fmaxf(c[0][1], 0.f)),
              tf32r(fmaxf(c[0][2], 0.f)), tf32r(fmaxf(c[0][3], 0.f)));
    storeFrag(dst, rowM, np * 16 + 8, lane,
              tf32r(fmaxf(c[1][0], 0.f)), tf32r(fmaxf(c[1][1], 0.f)),
              tf32r(fmaxf(c[1][2], 0.f)), tf32r(fmaxf(c[1][3], 0.f)));
    storeFrag(dst, rowM + 16, np * 16, lane,
              tf32r(fmaxf(c[2][0], 0.f)), tf32r(fmaxf(c[2][1], 0.f)),
              tf32r(fmaxf(c[2][2], 0.f)), tf32r(fmaxf(c[2][3], 0.f)));
    storeFrag(dst, rowM + 16, np * 16 + 8, lane,
              tf32r(fmaxf(c[3][0], 0.f)), tf32r(fmaxf(c[3][1], 0.f)),
              tf32r(fmaxf(c[3][2], 0.f)), tf32r(fmaxf(c[3][3], 0.f)));
}

// group barrier: 128 threads (4 warps), barrier id g+1 (4 groups)
#define GBAR() asm volatile("bar.sync %0, %1;" :: "r"(g + 1), "r"(128) : "memory")

__global__ void __launch_bounds__(512, 1)
nerf_mma(const float* __restrict__ x_feat, const float* __restrict__ dvec,
         const float* __restrict__ lvec, float* __restrict__ out,
         int N, int ntiles) {
    extern __shared__ float sm[];
    float* sW   = sm;
    float* B1   = sm + SM_B1;
    float* B2   = sm + SM_B2;
    float* visP = sm + SM_VISP;
    float* visR = sm + SM_VISR;

    int tid = threadIdx.x, wid = tid >> 5, lane = tid & 31;
    int g = wid >> 2;               // 4 groups of 4 warps, 64 rows each
    int w4 = wid & 3;
    int mi = w4 >> 1, ni = w4 & 1;  // 2x2 warp grid: m-half x n-half
    int rowG = g * 64;
    int rowW = rowG + mi * 32;      // warp's 32 rows (2 m-blocks)
    int t2 = tid & 127;

    {
        const float4* s = (const float4*)g_W;
        float4* d = (float4*)sW;
        for (int i = tid; i < W_TOTAL / 4; i += 512) d[i] = s[i];
    }
    __syncthreads();

    for (int tile = blockIdx.x; tile < ntiles; tile += gridDim.x) {
        // ---- phase 0: fill group's 64 rows of B1 (x | l_enc | d_enc) ----
        {
            if (t2 < 64) {
                int r = rowG + t2;
                int p = tile * 256 + r;
                int pc = (p < N) ? p : (N - 1);
                const float4* xp = (const float4*)(x_feat + 32 * (size_t)pc);
                float* dst = B1 + r * 68;
#pragma unroll
                for (int i = 0; i < 8; i++) {
                    float4 v = xp[i];
                    dst[4 * i]     = tf32r(v.x);
                    dst[4 * i + 1] = tf32r(v.y);
                    dst[4 * i + 2] = tf32r(v.z);
                    dst[4 * i + 3] = tf32r(v.w);
                }
                float e[16];
                const float* dp = dvec + 3 * (size_t)pc;
                sh16(dp[0], dp[1], dp[2], e);
#pragma unroll
                for (int i = 0; i < 16; i++) dst[48 + i] = tf32r(e[i]);
            } else {
                int r = rowG + t2 - 64;
                int p = tile * 256 + r;
                int pc = (p < N) ? p : (N - 1);
                float e[16];
                const float* lp = lvec + 3 * (size_t)pc;
                sh16(lp[0], lp[1], lp[2], e);
                float* dst = B1 + r * 68 + 32;
#pragma unroll
                for (int i = 0; i < 16; i++) dst[i] = tf32r(e[i]);
            }
        }
        GBAR();

        // ---- phase 1: hoist A (16 frags), GBAR, then sig0 / vis0(reg) / col0
        {
            unsigned a0[8][4], a1[8][4];
#pragma unroll
            for (int kt = 0; kt < 8; kt++) {
                loadA(a0[kt], B1 + rowW * 68, kt, lane);
                loadA(a1[kt], B1 + (rowW + 16) * 68, kt, lane);
            }
            GBAR();     // all hoists done; B1 stores now safe
            // sig0 -> B2
            layer2m<4>(a0, a1, sW + OFF_SIG0, 2 * ni,     B2, rowW, lane);
            layer2m<4>(a0, a1, sW + OFF_SIG0, 2 * ni + 1, B2, rowW, lane);
            // vis0 in registers -> vis partial dot with w_vis1
            {
                float va[4] = {0.f, 0.f, 0.f, 0.f};
                const float* wv = sW + OFF_V1L;
#pragma unroll
                for (int npi = 0; npi < 2; npi++) {
                    int np = 2 * ni + npi;
                    float c[4][4];
#pragma unroll
                    for (int i = 0; i < 4; i++)
#pragma unroll
                        for (int j = 0; j < 4; j++) c[i][j] = 0.f;
#pragma unroll
                    for (int kt = 0; kt < 6; kt++) {
                        float4 b = *(const float4*)(sW + OFF_VIS0 + (kt * 4 + np) * 128 + lane * 4);
                        mma8(c[0], a0[kt], b.x, b.y);
                        mma8(c[1], a0[kt], b.z, b.w);
                        mma8(c[2], a1[kt], b.x, b.y);
                        mma8(c[3], a1[kt], b.z, b.w);
                    }
                    int q2 = 2 * (lane & 3);
                    float2 wA = *(const float2*)(wv + np * 16 + q2);
                    float2 wB = *(const float2*)(wv + np * 16 + 8 + q2);
                    va[0] += fmaxf(c[0][0], 0.f) * wA.x + fmaxf(c[0][1], 0.f) * wA.y
                           + fmaxf(c[1][0], 0.f) * wB.x + fmaxf(c[1][1], 0.f) * wB.y;
                    va[1] += fmaxf(c[0][2], 0.f) * wA.x + fmaxf(c[0][3], 0.f) * wA.y
                           + fmaxf(c[1][2], 0.f) * wB.x + fmaxf(c[1][3], 0.f) * wB.y;
                    va[2] += fmaxf(c[2][0], 0.f) * wA.x + fmaxf(c[2][1], 0.f) * wA.y
                           + fmaxf(c[3][0], 0.f) * wB.x + fmaxf(c[3][1], 0.f) * wB.y;
                    va[3] += fmaxf(c[2][2], 0.f) * wA.x + fmaxf(c[2][3], 0.f) * wA.y
                           + fmaxf(c[3][2], 0.f) * wB.x + fmaxf(c[3][3], 0.f) * wB.y;
                }
#pragma unroll
                for (int m = 1; m <= 2; m <<= 1) {
#pragma unroll
                    for (int i = 0; i < 4; i++)
                        va[i] += __shfl_xor_sync(0xffffffffu, va[i], m);
                }
                if ((lane & 3) == 0) {
                    int r = lane >> 2;
                    visP[(rowW + r) * 2 + ni]      = va[0];
                    visP[(rowW + r + 8) * 2 + ni]  = va[1];
                    visP[(rowW + 16 + r) * 2 + ni] = va[2];
                    visP[(rowW + 24 + r) * 2 + ni] = va[3];
                }
            }
            // col0 -> B1 (inputs dead after hoist-GBAR)
            layer2m<8>(a0, a1, sW + OFF_COL0, 2 * ni,     B1, rowW, lane);
            layer2m<8>(a0, a1, sW + OFF_COL0, 2 * ni + 1, B1, rowW, lane);
        }
        GBAR();

        // ---- phase 2: each warp = one 16-row block: sig1 -> geo; vis finalize
        {
            int rowB = rowG + w4 * 16;
            unsigned a[8][4];
#pragma unroll
            for (int kt = 0; kt < 8; kt++) loadA(a[kt], B2 + rowB * 68, kt, lane);
            float c0[4] = {0.f, 0.f, 0.f, 0.f}, c1[4] = {0.f, 0.f, 0.f, 0.f};
#pragma unroll
            for (int kt = 0; kt < 8; kt++) {
                float4 b = *(const float4*)(sW + OFF_SIG1 + kt * 128 + lane * 4);
                mma8(c0, a[kt], b.x, b.y);
                mma8(c1, a[kt], b.z, b.w);
            }
            // geo: round, NO relu; overwrite sig_h cols 0..15 of own rows (hoisted)
            storeFrag(B2, rowB, 0, lane, tf32r(c0[0]), tf32r(c0[1]), tf32r(c0[2]), tf32r(c0[3]));
            storeFrag(B2, rowB, 8, lane, tf32r(c1[0]), tf32r(c1[1]), tf32r(c1[2]), tf32r(c1[3]));
            if (t2 < 64) {
                int r = rowG + t2;
                float v = visP[2 * r] + visP[2 * r + 1];
                visR[r] = __fdividef(1.f, 1.f + __expf(-v));
            }
        }
        GBAR();

        // ---- phase 3: col1 = relu(col0_h @ C1A + geo @ C1B) -> B2 ----
        {
            unsigned a0[8][4], a1[8][4], g0[2][4], g1[2][4];
#pragma unroll
            for (int kt = 0; kt < 8; kt++) {
                loadA(a0[kt], B1 + rowW * 68, kt, lane);
                loadA(a1[kt], B1 + (rowW + 16) * 68, kt, lane);
            }
#pragma unroll
            for (int kt = 0; kt < 2; kt++) {
                loadA(g0[kt], B2 + rowW * 68, kt, lane);
                loadA(g1[kt], B2 + (rowW + 16) * 68, kt, lane);
            }
            GBAR();     // all geo/col0_h hoists done; B2 stores now safe
#pragma unroll
            for (int npi = 0; npi < 2; npi++) {
                int np = 2 * ni + npi;
                float c[4][4];
#pragma unroll
                for (int i = 0; i < 4; i++)
#pragma unroll
                    for (int j = 0; j < 4; j++) c[i][j] = 0.f;
#pragma unroll
                for (int kt = 0; kt < 8; kt++) {
                    float4 b = *(const float4*)(sW + OFF_C1A + (kt * 4 + np) * 128 + lane * 4);
                    mma8(c[0], a0[kt], b.x, b.y);
                    mma8(c[1], a0[kt], b.z, b.w);
                    mma8(c[2], a1[kt], b.x, b.y);
                    mma8(c[3], a1[kt], b.z, b.w);
                }
#pragma unroll
                for (int kt = 0; kt < 2; kt++) {
                    float4 b = *(const float4*)(sW + OFF_C1B + (kt * 4 + np) * 128 + lane * 4);
                    mma8(c[0], g0[kt], b.x, b.y);
                    mma8(c[1], g0[kt], b.z, b.w);
                    mma8(c[2], g1[kt], b.x, b.y);
                    mma8(c[3], g1[kt], b.z, b.w);
                }
                storeFrag(B2, rowW, np * 16, lane,
                          tf32r(fmaxf(c[0][0], 0.f)), tf32r(fmaxf(c[0][1], 0.f)),
                          tf32r(fmaxf(c[0][2], 0.f)), tf32r(fmaxf(c[0][3], 0.f)));
                storeFrag(B2, rowW, np * 16 + 8, lane,
                          tf32r(fmaxf(c[1][0], 0.f)), tf32r(fmaxf(c[1][1], 0.f)),
                          tf32r(fmaxf(c[1][2], 0.f)), tf32r(fmaxf(c[1][3], 0.f)));
                storeFrag(B2, rowW + 16, np * 16, lane,
                          tf32r(fmaxf(c[2][0], 0.f)), tf32r(fmaxf(c[2][1], 0.f)),
                          tf32r(fmaxf(c[2][2], 0.f)), tf32r(fmaxf(c[2][3], 0.f)));
                storeFrag(B2, rowW + 16, np * 16 + 8, lane,
                          tf32r(fmaxf(c[3][0], 0.f)), tf32r(fmaxf(c[3][1], 0.f)),
                          tf32r(fmaxf(c[3][2], 0.f)), tf32r(fmaxf(c[3][3], 0.f)));
            }
        }
        GBAR();

        // ---- phase 4: col2 (3 real cols): ni = k-half; both m-blocks ----
        {
#pragma unroll
            for (int mb = 0; mb < 2; mb++) {
                int rb = rowW + mb * 16;
                unsigned a[4][4];
#pragma unroll
                for (int kt = 0; kt < 4; kt++)
                    loadA(a[kt], B2 + rb * 68, ni * 4 + kt, lane);
                float c0[4] = {0.f, 0.f, 0.f, 0.f};
#pragma unroll
                for (int kt = 0; kt < 4; kt++) {
                    float2 b = *(const float2*)(sW + OFF_COL2 + (ni * 4 + kt) * 128 + lane * 4);
                    mma8(c0, a[kt], b.x, b.y);
                }
                storeFrag(B1, rb, ni * 32, lane, c0[0], c0[1], c0[2], c0[3]);
            }
        }
        GBAR();

        // ---- epilogue: color = relu(p0+p1) * sigmoid(vis), group's 64 rows ----
        for (int i = t2; i < 192; i += 128) {
            int pp = rowG + i / 3, c = i % 3;
            int gg = tile * 256 + pp;
            if (gg < N) {
                float v = B1[pp * 68 + c] + B1[pp * 68 + 32 + c];
                out[3 * (size_t)gg + c] = fmaxf(v, 0.f) * visR[pp];
            }
        }
        GBAR();
    }
}

extern "C" void kernel_launch(void* const* d_in, const int* in_sizes, int n_in,
                              void* d_out, int out_size) {
    const float* x_feat = (const float*)d_in[0];
    const float* dv     = (const float*)d_in[1];
    const float* lv     = (const float*)d_in[2];
    const float* w_sig0 = (const float*)d_in[3];
    const float* w_sig1 = (const float*)d_in[4];
    const float* w_col0 = (const float*)d_in[5];
    const float* w_col1 = (const float*)d_in[6];
    const float* w_col2 = (const float*)d_in[7];
    const float* w_vis0 = (const float*)d_in[8];
    const float* w_vis1 = (const float*)d_in[9];
    float* out = (float*)d_out;
    int N = in_sizes[0] / 32;
    int ntiles = (N + 255) / 256;

    int dev = 0, smc = 148;
    cudaGetDevice(&dev);
    cudaDeviceGetAttribute(&smc, cudaDevAttrMultiProcessorCount, dev);
    int grid = (smc < ntiles) ? smc : ntiles;

    cudaFuncSetAttribute(nerf_mma, cudaFuncAttributeMaxDynamicSharedMemorySize,
                         SMEM_BYTES);

    prep_kernel<<<1, 256>>>(w_sig0, w_sig1, w_col0, w_col1, w_col2, w_vis0, w_vis1);
    nerf_mma<<<grid, 512, SMEM_BYTES>>>(x_feat, dv, lv, out, N, ntiles);
}

// round 15
// speedup vs baseline: 3.9297x; 1.6810x over previous
#include <cuda_runtime.h>
#include <cuda_fp16.h>
#include <cstdint>

// ------------- weight layout: f16 mma-fragment-packed blocks (uints) -------
// Wide block (kt, np) = 128 uints: lane*4 + {b0_j0, b1_j0, b0_j1, b1_j1}
// b0 = half2{B[kt*16+2q][n], B[kt*16+2q+1][n]}, b1 = rows +8,+9; n = np*16+j*8+r
#define OFF_COL0 0          // 4 kt x 4 np
#define OFF_VIS0 2048       // 3 x 4
#define OFF_SIG0 3584       // 2 x 4
#define OFF_C1A  4608       // 4 x 4
#define OFF_C1B  6656       // 1 x 4 (k row0 zero, rows 1..15 = col1 rows 64..78)
#define OFF_SIG1 7168       // 4 kt x 1 np
#define OFF_COL2 7680       // 4 kt x 64 uints (single n8, n<3 real)
#define OFF_V1L  7936       // 64 f32 (vis1 weights, stored as bits)
#define W_TOTAL  8192

__device__ __align__(16) unsigned g_W[W_TOTAL];

__device__ void packB16(unsigned* dst, const float* W, int Kreal, int Nreal,
                        int KT, int NP, int t, int st) {
    for (int idx = t; idx < KT * NP * 128; idx += st) {
        int blk = idx >> 7, w = idx & 127;
        int lane = w >> 2, j2 = w & 3;
        int j = j2 >> 1, which = j2 & 1;
        int kt = blk / NP, np = blk % NP;
        int r = lane >> 2, q = lane & 3;
        int n = np * 16 + j * 8 + r;
        int k0 = kt * 16 + 2 * q + which * 8;
        float v0 = (k0 < Kreal && n < Nreal) ? W[k0 * Nreal + n] : 0.f;
        float v1 = (k0 + 1 < Kreal && n < Nreal) ? W[(k0 + 1) * Nreal + n] : 0.f;
        __half2 h = __floats2half2_rn(v0, v1);
        dst[idx] = *(unsigned*)&h;
    }
}

__global__ void prep_kernel(const float* __restrict__ ws0, const float* __restrict__ ws1,
                            const float* __restrict__ wc0, const float* __restrict__ wc1,
                            const float* __restrict__ wc2, const float* __restrict__ wv0,
                            const float* __restrict__ wv1) {
    int t = threadIdx.x;
    packB16(g_W + OFF_COL0, wc0, 64, 64, 4, 4, t, 256);
    packB16(g_W + OFF_VIS0, wv0, 48, 64, 3, 4, t, 256);
    packB16(g_W + OFF_SIG0, ws0, 32, 64, 2, 4, t, 256);
    packB16(g_W + OFF_C1A,  wc1, 64, 64, 4, 4, t, 256);
    packB16(g_W + OFF_SIG1, ws1, 64, 16, 4, 1, t, 256);
    // C1B: logical 16xK rows, row0 = 0, row k = wc1[(63+k)][n]
    for (int idx = t; idx < 512; idx += 256) {
        int w = idx & 127;
        int lane = w >> 2, j2 = w & 3;
        int j = j2 >> 1, which = j2 & 1;
        int np = idx >> 7;
        int r = lane >> 2, q = lane & 3;
        int n = np * 16 + j * 8 + r;
        int k0 = 2 * q + which * 8;
        float v0 = (k0 >= 1 && k0 < 16) ? wc1[(63 + k0) * 64 + n] : 0.f;
        float v1 = (k0 + 1 >= 1 && k0 + 1 < 16) ? wc1[(63 + k0 + 1) * 64 + n] : 0.f;
        __half2 h = __floats2half2_rn(v0, v1);
        g_W[OFF_C1B + idx] = *(unsigned*)&h;
    }
    // COL2: single n8 blocks, 64 uints each
    for (int idx = t; idx < 256; idx += 256) {
        ;
    }
    for (int idx = t; idx < 256; idx += 256) { }
    for (int idx = t; idx < 256; idx += 256) { }
    for (int idx = t; idx < 4 * 64; idx += 256) {
        int kt = idx >> 6, w = idx & 63;
        int lane = w >> 1, which = w & 1;
        int r = lane >> 2, q = lane & 3;
        int n = r;
        int k0 = kt * 16 + 2 * q + which * 8;
        float v0 = (n < 3) ? wc2[k0 * 3 + n] : 0.f;
        float v1 = (n < 3) ? wc2[(k0 + 1) * 3 + n] : 0.f;
        __half2 h = __floats2half2_rn(v0, v1);
        g_W[OFF_COL2 + idx] = *(unsigned*)&h;
    }
    for (int i = t; i < 256; i += 256) {
        g_W[OFF_V1L + i] = (i < 64) ? __float_as_uint(wv1[i]) : 0u;
    }
}

// ---------------- SH degree-4 ----------------
__device__ __forceinline__ void sh16(float x, float y, float z, float* e) {
    float xx = x * x, yy = y * y, zz = z * z;
    float xy = x * y, yz = y * z, xz = x * z;
    e[0]  = 0.28209479177387814f;
    e[1]  = -0.48860251190291987f * y;
    e[2]  = 0.48860251190291987f * z;
    e[3]  = -0.48860251190291987f * x;
    e[4]  = 1.0925484305920792f * xy;
    e[5]  = -1.0925484305920792f * yz;
    e[6]  = 0.94617469575756f * zz - 0.31539156525252005f;
    e[7]  = -1.0925484305920792f * xz;
    e[8]  = 0.5462742152960396f * (xx - yy);
    e[9]  = 0.5900435899266435f * y * (3.0f * xx - yy);
    e[10] = 2.890611442640554f * xy * z;
    e[11] = 0.4570457994644657f * y * (4.0f * zz - xx - yy);
    e[12] = 0.3731763325901154f * z * (2.0f * zz - 3.0f * xx - 3.0f * yy);
    e[13] = 0.4570457994644657f * x * (4.0f * zz - xx - yy);
    e[14] = 1.445305721320277f * z * (xx - yy);
    e[15] = 0.5900435899266435f * x * (xx - 3.0f * yy);
}

// ---- smem layout (float indices): weights 8192, then f16 row-buffers -----
#define SM_B1    8192               // [256][72] halfs = 9216 floats
#define SM_B2    17408              // [256][72] halfs
#define SM_VISP  26624              // [256][2] f32
#define SM_VISR  27136              // [256] f32
#define SM_COLP  27392              // [256][16] f32
#define SM_TOTAL 31488
#define SMEM_BYTES (SM_TOTAL * 4)

// ---------------- raw f16 mma helpers ----------------
__device__ __forceinline__ void mma16(float* c, const unsigned* a, unsigned b0, unsigned b1) {
    asm volatile(
        "mma.sync.aligned.m16n8k16.row.col.f32.f16.f16.f32 "
        "{%0,%1,%2,%3}, {%4,%5,%6,%7}, {%8,%9}, {%0,%1,%2,%3};"
        : "+f"(c[0]), "+f"(c[1]), "+f"(c[2]), "+f"(c[3])
        : "r"(a[0]), "r"(a[1]), "r"(a[2]), "r"(a[3]), "r"(b0), "r"(b1));
}

__device__ __forceinline__ void loadA16(unsigned* a, const __half* Ab, int kt, int lane) {
    int r = lane >> 2, q = lane & 3;
    const __half* p = Ab + r * 72 + kt * 16 + 2 * q;
    a[0] = *(const unsigned*)(p);
    a[1] = *(const unsigned*)(p + 8 * 72);
    a[2] = *(const unsigned*)(p + 8);
    a[3] = *(const unsigned*)(p + 8 * 72 + 8);
}

__device__ __forceinline__ void storeF16(__half* dst, int row0, int cbase, int lane,
                                         float c0, float c1, float c2, float c3) {
    int r = lane >> 2, q = lane & 3;
    __half2 lo = __floats2half2_rn(c0, c1);
    __half2 hi = __floats2half2_rn(c2, c3);
    *(unsigned*)(dst + (row0 + r) * 72 + cbase + 2 * q) = *(unsigned*)&lo;
    *(unsigned*)(dst + (row0 + r + 8) * 72 + cbase + 2 * q) = *(unsigned*)&hi;
}

// one layer, one npair, TWO m-blocks sharing each B load; relu store
template <int KT>
__device__ __forceinline__ void layer2m16(const unsigned a0[][4], const unsigned a1[][4],
                                          const unsigned* B, int np, __half* dst,
                                          int rowM, int lane) {
    float c[4][4];
#pragma unroll
    for (int i = 0; i < 4; i++)
#pragma unroll
        for (int j = 0; j < 4; j++) c[i][j] = 0.f;
#pragma unroll
    for (int kt = 0; kt < KT; kt++) {
        uint4 b = *(const uint4*)(B + (kt * 4 + np) * 128 + lane * 4);
        mma16(c[0], a0[kt], b.x, b.y);
        mma16(c[1], a0[kt], b.z, b.w);
        mma16(c[2], a1[kt], b.x, b.y);
        mma16(c[3], a1[kt], b.z, b.w);
    }
    storeF16(dst, rowM, np * 16, lane,
             fmaxf(c[0][0], 0.f), fmaxf(c[0][1], 0.f), fmaxf(c[0][2], 0.f), fmaxf(c[0][3], 0.f));
    storeF16(dst, rowM, np * 16 + 8, lane,
             fmaxf(c[1][0], 0.f), fmaxf(c[1][1], 0.f), fmaxf(c[1][2], 0.f), fmaxf(c[1][3], 0.f));
    storeF16(dst, rowM + 16, np * 16, lane,
             fmaxf(c[2][0], 0.f), fmaxf(c[2][1], 0.f), fmaxf(c[2][2], 0.f), fmaxf(c[2][3], 0.f));
    storeF16(dst, rowM + 16, np * 16 + 8, lane,
             fmaxf(c[3][0], 0.f), fmaxf(c[3][1], 0.f), fmaxf(c[3][2], 0.f), fmaxf(c[3][3], 0.f));
}

// group barrier: 128 threads (4 warps), barrier id g+1 (4 groups)
#define GBAR() asm volatile("bar.sync %0, %1;" :: "r"(g + 1), "r"(128) : "memory")

__global__ void __launch_bounds__(512, 1)
nerf_mma(const float* __restrict__ x_feat, const float* __restrict__ dvec,
         const float* __restrict__ lvec, float* __restrict__ out,
         int N, int ntiles) {
    extern __shared__ float sm[];
    unsigned* sW = (unsigned*)sm;
    __half* B1   = (__half*)(sm + SM_B1);
    __half* B2   = (__half*)(sm + SM_B2);
    float* visP  = sm + SM_VISP;
    float* visR  = sm + SM_VISR;
    float* colP  = sm + SM_COLP;

    int tid = threadIdx.x, wid = tid >> 5, lane = tid & 31;
    int g = wid >> 2;               // 4 groups of 4 warps, 64 rows each
    int w4 = wid & 3;
    int mi = w4 >> 1, ni = w4 & 1;  // 2x2 warp grid
    int rowG = g * 64;
    int rowW = rowG + mi * 32;      // warp's 32 rows (2 m-blocks)
    int t2 = tid & 127;

    {
        const uint4* s = (const uint4*)g_W;
        uint4* d = (uint4*)sW;
        for (int i = tid; i < W_TOTAL / 4; i += 512) d[i] = s[i];
    }
    __syncthreads();

    for (int tile = blockIdx.x; tile < ntiles; tile += gridDim.x) {
        // ---- phase 0: fill group's 64 rows of B1 (x | l_enc | d_enc), f16 ----
        {
            if (t2 < 64) {
                int r = rowG + t2;
                int p = tile * 256 + r;
                int pc = (p < N) ? p : (N - 1);
                const float4* xp = (const float4*)(x_feat + 32 * (size_t)pc);
                unsigned* dst = (unsigned*)(B1 + r * 72);
#pragma unroll
                for (int i = 0; i < 8; i++) {
                    float4 v = xp[i];
                    __half2 h0 = __floats2half2_rn(v.x, v.y);
                    __half2 h1 = __floats2half2_rn(v.z, v.w);
                    dst[2 * i]     = *(unsigned*)&h0;
                    dst[2 * i + 1] = *(unsigned*)&h1;
                }
                float e[16];
                const float* dp = dvec + 3 * (size_t)pc;
                sh16(dp[0], dp[1], dp[2], e);
#pragma unroll
                for (int i = 0; i < 8; i++) {
                    __half2 h = __floats2half2_rn(e[2 * i], e[2 * i + 1]);
                    dst[24 + i] = *(unsigned*)&h;
                }
            } else {
                int r = rowG + t2 - 64;
                int p = tile * 256 + r;
                int pc = (p < N) ? p : (N - 1);
                float e[16];
                const float* lp = lvec + 3 * (size_t)pc;
                sh16(lp[0], lp[1], lp[2], e);
                unsigned* dst = (unsigned*)(B1 + r * 72);
#pragma unroll
                for (int i = 0; i < 8; i++) {
                    __half2 h = __floats2half2_rn(e[2 * i], e[2 * i + 1]);
                    dst[16 + i] = *(unsigned*)&h;
                }
            }
        }
        GBAR();

        // ---- phase 1: hoist A (8 frags), GBAR, sig0 / vis0(reg) / col0 ----
        {
            unsigned a0[4][4], a1[4][4];
#pragma unroll
            for (int kt = 0; kt < 4; kt++) {
                loadA16(a0[kt], B1 + rowW * 72, kt, lane);
                loadA16(a1[kt], B1 + (rowW + 16) * 72, kt, lane);
            }
            GBAR();     // hoists done; B1 stores now safe
            layer2m16<2>(a0, a1, sW + OFF_SIG0, 2 * ni,     B2, rowW, lane);
            layer2m16<2>(a0, a1, sW + OFF_SIG0, 2 * ni + 1, B2, rowW, lane);
            // vis0 in registers -> partial dot with w_vis1 (fp32)
            {
                float va[4] = {0.f, 0.f, 0.f, 0.f};
                const float* wv = (const float*)(sW + OFF_V1L);
#pragma unroll
                for (int npi = 0; npi < 2; npi++) {
                    int np = 2 * ni + npi;
                    float c[4][4];
#pragma unroll
                    for (int i = 0; i < 4; i++)
#pragma unroll
                        for (int j = 0; j < 4; j++) c[i][j] = 0.f;
#pragma unroll
                    for (int kt = 0; kt < 3; kt++) {
                        uint4 b = *(const uint4*)(sW + OFF_VIS0 + (kt * 4 + np) * 128 + lane * 4);
                        mma16(c[0], a0[kt], b.x, b.y);
                        mma16(c[1], a0[kt], b.z, b.w);
                        mma16(c[2], a1[kt], b.x, b.y);
                        mma16(c[3], a1[kt], b.z, b.w);
                    }
                    int q2 = 2 * (lane & 3);
                    float2 wA = *(const float2*)(wv + np * 16 + q2);
                    float2 wB = *(const float2*)(wv + np * 16 + 8 + q2);
                    va[0] += fmaxf(c[0][0], 0.f) * wA.x + fmaxf(c[0][1], 0.f) * wA.y
                           + fmaxf(c[1][0], 0.f) * wB.x + fmaxf(c[1][1], 0.f) * wB.y;
                    va[1] += fmaxf(c[0][2], 0.f) * wA.x + fmaxf(c[0][3], 0.f) * wA.y
                           + fmaxf(c[1][2], 0.f) * wB.x + fmaxf(c[1][3], 0.f) * wB.y;
                    va[2] += fmaxf(c[2][0], 0.f) * wA.x + fmaxf(c[2][1], 0.f) * wA.y
                           + fmaxf(c[3][0], 0.f) * wB.x + fmaxf(c[3][1], 0.f) * wB.y;
                    va[3] += fmaxf(c[2][2], 0.f) * wA.x + fmaxf(c[2][3], 0.f) * wA.y
                           + fmaxf(c[3][2], 0.f) * wB.x + fmaxf(c[3][3], 0.f) * wB.y;
                }
#pragma unroll
                for (int m = 1; m <= 2; m <<= 1) {
#pragma unroll
                    for (int i = 0; i < 4; i++)
                        va[i] += __shfl_xor_sync(0xffffffffu, va[i], m);
                }
                if ((lane & 3) == 0) {
                    int r = lane >> 2;
                    visP[(rowW + r) * 2 + ni]      = va[0];
                    visP[(rowW + r + 8) * 2 + ni]  = va[1];
                    visP[(rowW + 16 + r) * 2 + ni] = va[2];
                    visP[(rowW + 24 + r) * 2 + ni] = va[3];
                }
            }
            layer2m16<4>(a0, a1, sW + OFF_COL0, 2 * ni,     B1, rowW, lane);
            layer2m16<4>(a0, a1, sW + OFF_COL0, 2 * ni + 1, B1, rowW, lane);
        }
        GBAR();

        // ---- phase 2: warp = one 16-row block: sig1 -> geo; vis finalize ----
        {
            int rowB = rowG + w4 * 16;
            unsigned a[4][4];
#pragma unroll
            for (int kt = 0; kt < 4; kt++) loadA16(a[kt], B2 + rowB * 72, kt, lane);
            float c0[4] = {0.f, 0.f, 0.f, 0.f}, c1[4] = {0.f, 0.f, 0.f, 0.f};
#pragma unroll
            for (int kt = 0; kt < 4; kt++) {
                uint4 b = *(const uint4*)(sW + OFF_SIG1 + kt * 128 + lane * 4);
                mma16(c0, a[kt], b.x, b.y);
                mma16(c1, a[kt], b.z, b.w);
            }
            // geo: NO relu (f16 store rounds)
            storeF16(B2, rowB, 0, lane, c0[0], c0[1], c0[2], c0[3]);
            storeF16(B2, rowB, 8, lane, c1[0], c1[1], c1[2], c1[3]);
            if (t2 < 64) {
                int r = rowG + t2;
                float v = visP[2 * r] + visP[2 * r + 1];
                visR[r] = __fdividef(1.f, 1.f + __expf(-v));
            }
        }
        GBAR();

        // ---- phase 3: col1 = relu(col0_h @ C1A + geo @ C1B) -> B2 ----
        {
            unsigned a0[4][4], a1[4][4], g0[4], g1[4];
#pragma unroll
            for (int kt = 0; kt < 4; kt++) {
                loadA16(a0[kt], B1 + rowW * 72, kt, lane);
                loadA16(a1[kt], B1 + (rowW + 16) * 72, kt, lane);
            }
            loadA16(g0, B2 + rowW * 72, 0, lane);
            loadA16(g1, B2 + (rowW + 16) * 72, 0, lane);
            GBAR();     // hoists done; B2 stores now safe
#pragma unroll
            for (int npi = 0; npi < 2; npi++) {
                int np = 2 * ni + npi;
                float c[4][4];
#pragma unroll
                for (int i = 0; i < 4; i++)
#pragma unroll
                    for (int j = 0; j < 4; j++) c[i][j] = 0.f;
#pragma unroll
                for (int kt = 0; kt < 4; kt++) {
                    uint4 b = *(const uint4*)(sW + OFF_C1A + (kt * 4 + np) * 128 + lane * 4);
                    mma16(c[0], a0[kt], b.x, b.y);
                    mma16(c[1], a0[kt], b.z, b.w);
                    mma16(c[2], a1[kt], b.x, b.y);
                    mma16(c[3], a1[kt], b.z, b.w);
                }
                {
                    uint4 b = *(const uint4*)(sW + OFF_C1B + np * 128 + lane * 4);
                    mma16(c[0], g0, b.x, b.y);
                    mma16(c[1], g0, b.z, b.w);
                    mma16(c[2], g1, b.x, b.y);
                    mma16(c[3], g1, b.z, b.w);
                }
                storeF16(B2, rowW, np * 16, lane,
                         fmaxf(c[0][0], 0.f), fmaxf(c[0][1], 0.f),
                         fmaxf(c[0][2], 0.f), fmaxf(c[0][3], 0.f));
                storeF16(B2, rowW, np * 16 + 8, lane,
                         fmaxf(c[1][0], 0.f), fmaxf(c[1][1], 0.f),
                         fmaxf(c[1][2], 0.f), fmaxf(c[1][3], 0.f));
                storeF16(B2, rowW + 16, np * 16, lane,
                         fmaxf(c[2][0], 0.f), fmaxf(c[2][1], 0.f),
                         fmaxf(c[2][2], 0.f), fmaxf(c[2][3], 0.f));
                storeF16(B2, rowW + 16, np * 16 + 8, lane,
                         fmaxf(c[3][0], 0.f), fmaxf(c[3][1], 0.f),
                         fmaxf(c[3][2], 0.f), fmaxf(c[3][3], 0.f));
            }
        }
        GBAR();

        // ---- phase 4: col2: ni = k-half (kt 2 each); both m-blocks -> colP f32
        {
            int r = lane >> 2, q = lane & 3;
#pragma unroll
            for (int mb = 0; mb < 2; mb++) {
                int rb = rowW + mb * 16;
                unsigned a[2][4];
#pragma unroll
                for (int kt = 0; kt < 2; kt++)
                    loadA16(a[kt], B2 + rb * 72, ni * 2 + kt, lane);
                float c0[4] = {0.f, 0.f, 0.f, 0.f};
#pragma unroll
                for (int kt = 0; kt < 2; kt++) {
                    uint2 b = *(const uint2*)(sW + OFF_COL2 + (ni * 2 + kt) * 64 + lane * 2);
                    mma16(c0, a[kt], b.x, b.y);
                }
                *(float2*)(colP + (rb + r) * 16 + ni * 8 + 2 * q) = make_float2(c0[0], c0[1]);
                *(float2*)(colP + (rb + r + 8) * 16 + ni * 8 + 2 * q) = make_float2(c0[2], c0[3]);
            }
        }
        GBAR();

        // ---- epilogue: color = relu(p0+p1) * sigmoid(vis), group's 64 rows ----
        for (int i = t2; i < 192; i += 128) {
            int pp = rowG + i / 3, c = i % 3;
            int gg = tile * 256 + pp;
            if (gg < N) {
                float v = colP[pp * 16 + c] + colP[pp * 16 + 8 + c];
                out[3 * (size_t)gg + c] = fmaxf(v, 0.f) * visR[pp];
            }
        }
        GBAR();
    }
}

extern "C" void kernel_launch(void* const* d_in, const int* in_sizes, int n_in,
                              void* d_out, int out_size) {
    const float* x_feat = (const float*)d_in[0];
    const float* dv     = (const float*)d_in[1];
    const float* lv     = (const float*)d_in[2];
    const float* w_sig0 = (const float*)d_in[3];
    const float* w_sig1 = (const float*)d_in[4];
    const float* w_col0 = (const float*)d_in[5];
    const float* w_col1 = (const float*)d_in[6];
    const float* w_col2 = (const float*)d_in[7];
    const float* w_vis0 = (const float*)d_in[8];
    const float* w_vis1 = (const float*)d_in[9];
    float* out = (float*)d_out;
    int N = in_sizes[0] / 32;
    int ntiles = (N + 255) / 256;

    int dev = 0, smc = 148;
    cudaGetDevice(&dev);
    cudaDeviceGetAttribute(&smc, cudaDevAttrMultiProcessorCount, dev);
    int grid = (smc < ntiles) ? smc : ntiles;

    cudaFuncSetAttribute(nerf_mma, cudaFuncAttributeMaxDynamicSharedMemorySize,
                         SMEM_BYTES);

    prep_kernel<<<1, 256>>>(w_sig0, w_sig1, w_col0, w_col1, w_col2, w_vis0, w_vis1);
    nerf_mma<<<grid, 512, SMEM_BYTES>>>(x_feat, dv, lv, out, N, ntiles);
}